// round 1
// baseline (speedup 1.0000x reference)
#include <cuda_runtime.h>
#include <cstddef>

#define N_TXN 100000
#define N_CLI 20000
#define N_E   600000
#define HDIM  128

// ---------------- static scratch (no allocations allowed) ----------------
// int scratch layout
#define I_CNT_TXN 0
#define I_CNT_CLI (I_CNT_TXN + N_TXN)
#define I_OFF_TXN (I_CNT_CLI + N_CLI)
#define I_OFF_CLI (I_OFF_TXN + N_TXN)
#define I_CUR_TXN (I_OFF_CLI + N_CLI)
#define I_CUR_CLI (I_CUR_TXN + N_TXN)
#define I_SRC_CT  (I_CUR_CLI + N_CLI)
#define I_SRC_TC  (I_SRC_CT + N_E)
#define I_TOTAL   (I_SRC_TC + N_E)

// float scratch layout
#define F_MEAN1_TXN 0                                        // N_TXN*32
#define F_MEAN1_CLI (F_MEAN1_TXN + (size_t)N_TXN*32)         // N_CLI*64
#define F_H_TXN     (F_MEAN1_CLI + (size_t)N_CLI*64)         // N_TXN*128
#define F_H_CLI     (F_H_TXN + (size_t)N_TXN*HDIM)           // N_CLI*128
#define F_PRE       (F_H_CLI + (size_t)N_CLI*HDIM)           // N_CLI*128
#define F_MEAN2_TXN (F_PRE + (size_t)N_CLI*HDIM)             // N_TXN*128
#define F_MEAN2_CLI (F_MEAN2_TXN + (size_t)N_TXN*HDIM)       // N_CLI*128
#define F_DEC       (F_MEAN2_CLI + (size_t)N_CLI*HDIM)       // N_TXN*64
#define F_TOTAL     (F_DEC + (size_t)N_TXN*64)

__device__ int   g_iscratch[I_TOTAL];
__device__ float g_fscratch[F_TOTAL];

// ---------------- CSR build ----------------
__global__ void zero_cnt_kernel(int* __restrict__ cnt_txn, int* __restrict__ cnt_cli) {
    int i = blockIdx.x * blockDim.x + threadIdx.x;
    if (i < N_TXN) cnt_txn[i] = 0;
    if (i < N_CLI) cnt_cli[i] = 0;
}

__global__ void count_kernel(const int* __restrict__ ct_dst, const int* __restrict__ tc_dst,
                             int* __restrict__ cnt_txn, int* __restrict__ cnt_cli) {
    int e = blockIdx.x * blockDim.x + threadIdx.x;
    if (e < N_E) {
        atomicAdd(&cnt_txn[ct_dst[e]], 1);
        atomicAdd(&cnt_cli[tc_dst[e]], 1);
    }
}

__device__ void scan_one(const int* __restrict__ cnt, int* __restrict__ off,
                         int* __restrict__ cur, int n, int* s) {
    int tid = threadIdx.x;
    __shared__ int sbase;
    if (tid == 0) sbase = 0;
    __syncthreads();
    for (int start = 0; start < n; start += 1024) {
        int i = start + tid;
        int v = (i < n) ? cnt[i] : 0;
        s[tid] = v;
        __syncthreads();
        for (int d = 1; d < 1024; d <<= 1) {
            int t = (tid >= d) ? s[tid - d] : 0;
            __syncthreads();
            if (tid >= d) s[tid] += t;
            __syncthreads();
        }
        int excl = sbase + s[tid] - v;
        int total = s[1023];
        if (i < n) { off[i] = excl; cur[i] = excl; }
        __syncthreads();
        if (tid == 0) sbase += total;
        __syncthreads();
    }
}

__global__ void scan_kernel(const int* cnt_txn, int* off_txn, int* cur_txn,
                            const int* cnt_cli, int* off_cli, int* cur_cli) {
    __shared__ int s[1024];
    scan_one(cnt_txn, off_txn, cur_txn, N_TXN, s);
    scan_one(cnt_cli, off_cli, cur_cli, N_CLI, s);
}

__global__ void fill_kernel(const int* __restrict__ ct_src, const int* __restrict__ ct_dst,
                            const int* __restrict__ tc_src, const int* __restrict__ tc_dst,
                            int* __restrict__ cur_txn, int* __restrict__ cur_cli,
                            int* __restrict__ src_ct, int* __restrict__ src_tc) {
    int e = blockIdx.x * blockDim.x + threadIdx.x;
    if (e < N_E) {
        int p = atomicAdd(&cur_txn[ct_dst[e]], 1);
        src_ct[p] = ct_src[e];
        int q = atomicAdd(&cur_cli[tc_dst[e]], 1);
        src_tc[q] = tc_src[e];
    }
}

// ---------------- warp-per-node mean gather ----------------
template <int F>  // F in {32, 64, 128}
__global__ void mean_gather_kernel(const float* __restrict__ table,
                                   const int* __restrict__ srcs,
                                   const int* __restrict__ off,
                                   const int* __restrict__ cnt,
                                   float* __restrict__ out, int n) {
    int gw = (blockIdx.x * blockDim.x + threadIdx.x) >> 5;
    int lane = threadIdx.x & 31;
    int nw = (gridDim.x * blockDim.x) >> 5;
    for (int i = gw; i < n; i += nw) {
        int o = off[i], c = cnt[i];
        float inv = 1.0f / fmaxf((float)c, 1.0f);
        if (F == 128) {
            float4 acc = make_float4(0.f, 0.f, 0.f, 0.f);
            for (int e = 0; e < c; e++) {
                int s = __ldg(&srcs[o + e]);
                float4 v = *reinterpret_cast<const float4*>(table + (size_t)s * 128 + lane * 4);
                acc.x += v.x; acc.y += v.y; acc.z += v.z; acc.w += v.w;
            }
            acc.x *= inv; acc.y *= inv; acc.z *= inv; acc.w *= inv;
            *reinterpret_cast<float4*>(out + (size_t)i * 128 + lane * 4) = acc;
        } else if (F == 64) {
            float2 acc = make_float2(0.f, 0.f);
            for (int e = 0; e < c; e++) {
                int s = __ldg(&srcs[o + e]);
                float2 v = *reinterpret_cast<const float2*>(table + (size_t)s * 64 + lane * 2);
                acc.x += v.x; acc.y += v.y;
            }
            acc.x *= inv; acc.y *= inv;
            *reinterpret_cast<float2*>(out + (size_t)i * 64 + lane * 2) = acc;
        } else {
            float acc = 0.f;
            for (int e = 0; e < c; e++) {
                int s = __ldg(&srcs[o + e]);
                acc += table[(size_t)s * 32 + lane];
            }
            out[(size_t)i * 32 + lane] = acc * inv;
        }
    }
}

// ---------------- fused dual SGEMM with epilogue ----------------
// C[M x TN] = act( A1[M x K1] @ W1[K1 x TN] (+ A2 @ W2) (+ bias) (+ addend) )
template <int K1, int K2, int TN, bool RELU, bool HASADD>
__global__ __launch_bounds__(256) void gemm_kernel(
    const float* __restrict__ A1, const float* __restrict__ W1,
    const float* __restrict__ A2, const float* __restrict__ W2,
    const float* __restrict__ bias, const float* __restrict__ addend,
    float* __restrict__ C, int M) {
    constexpr int TM = 64, KC = 32, NR = TN / 16;
    __shared__ float As[TM][KC];
    __shared__ float Ws[KC][TN];
    const int tid = threadIdx.x;
    const int m0 = blockIdx.x * TM;
    const int rt = tid >> 4;   // 0..15 (row group)
    const int ct = tid & 15;   // 0..15 (col group)

    float acc[4][NR];
#pragma unroll
    for (int i = 0; i < 4; i++)
#pragma unroll
        for (int j = 0; j < NR; j++) acc[i][j] = 0.f;

    auto run_piece = [&](const float* __restrict__ A, const float* __restrict__ W, int K) {
        for (int kc = 0; kc < K; kc += KC) {
            // load A tile [64 x 32]
            for (int i = tid; i < TM * KC / 4; i += 256) {
                int r = i >> 3, seg = i & 7;
                int m = m0 + r;
                float4 v = make_float4(0.f, 0.f, 0.f, 0.f);
                if (m < M) v = *reinterpret_cast<const float4*>(A + (size_t)m * K + kc + seg * 4);
                *reinterpret_cast<float4*>(&As[r][seg * 4]) = v;
            }
            // load W tile [32 x TN]
            for (int i = tid; i < KC * TN / 4; i += 256) {
                int k = i / (TN / 4), c = i % (TN / 4);
                *reinterpret_cast<float4*>(&Ws[k][c * 4]) =
                    *reinterpret_cast<const float4*>(W + (size_t)(kc + k) * TN + c * 4);
            }
            __syncthreads();
#pragma unroll
            for (int k = 0; k < KC; k++) {
                float a[4];
#pragma unroll
                for (int i = 0; i < 4; i++) a[i] = As[rt * 4 + i][k];
                float w[NR];
#pragma unroll
                for (int j = 0; j < NR; j += 4)
                    *reinterpret_cast<float4*>(&w[j]) =
                        *reinterpret_cast<const float4*>(&Ws[k][ct * NR + j]);
#pragma unroll
                for (int i = 0; i < 4; i++)
#pragma unroll
                    for (int j = 0; j < NR; j++) acc[i][j] += a[i] * w[j];
            }
            __syncthreads();
        }
    };

    run_piece(A1, W1, K1);
    if (K2 > 0) run_piece(A2, W2, K2);

    // epilogue
#pragma unroll
    for (int i = 0; i < 4; i++) {
        int m = m0 + rt * 4 + i;
        if (m >= M) continue;
        float v[NR];
#pragma unroll
        for (int j = 0; j < NR; j++) {
            float x = acc[i][j];
            if (bias) x += bias[ct * NR + j];
            if (HASADD) x += addend[(size_t)m * TN + ct * NR + j];
            if (RELU) x = fmaxf(x, 0.f);
            v[j] = x;
        }
#pragma unroll
        for (int j = 0; j < NR; j += 4)
            *reinterpret_cast<float4*>(C + (size_t)m * TN + ct * NR + j) =
                *reinterpret_cast<const float4*>(&v[j]);
    }
}

// ---------------- launch ----------------
extern "C" void kernel_launch(void* const* d_in, const int* in_sizes, int n_in,
                              void* d_out, int out_size) {
    const float* x_txn   = (const float*)d_in[0];
    const float* x_cli   = (const float*)d_in[1];
    const int*   ct_src  = (const int*)d_in[2];
    const int*   ct_dst  = (const int*)d_in[3];
    const int*   tc_src  = (const int*)d_in[4];
    const int*   tc_dst  = (const int*)d_in[5];
    const float* W1_ct_l = (const float*)d_in[6];
    const float* b1_ct   = (const float*)d_in[7];
    const float* W1_ct_r = (const float*)d_in[8];
    const float* W1_tc_l = (const float*)d_in[9];
    const float* b1_tc   = (const float*)d_in[10];
    const float* W1_tc_r = (const float*)d_in[11];
    const float* W2_ct_l = (const float*)d_in[12];
    const float* b2_ct   = (const float*)d_in[13];
    const float* W2_ct_r = (const float*)d_in[14];
    const float* W2_tc_l = (const float*)d_in[15];
    const float* b2_tc   = (const float*)d_in[16];
    const float* W2_tc_r = (const float*)d_in[17];
    const float* Wd1     = (const float*)d_in[18];
    const float* bd1     = (const float*)d_in[19];
    const float* Wd2     = (const float*)d_in[20];
    const float* bd2     = (const float*)d_in[21];

    float* out = (float*)d_out;
    float* recon = out;                                  // [N_TXN x 64]
    float* z_txn = out + (size_t)N_TXN * 64;             // [N_TXN x 128]
    float* z_cli = z_txn + (size_t)N_TXN * 128;          // [N_CLI x 128]

    void* p = nullptr;
    cudaGetSymbolAddress(&p, g_iscratch);
    int* I = (int*)p;
    cudaGetSymbolAddress(&p, g_fscratch);
    float* F = (float*)p;

    int* cnt_txn = I + I_CNT_TXN;
    int* cnt_cli = I + I_CNT_CLI;
    int* off_txn = I + I_OFF_TXN;
    int* off_cli = I + I_OFF_CLI;
    int* cur_txn = I + I_CUR_TXN;
    int* cur_cli = I + I_CUR_CLI;
    int* src_ct  = I + I_SRC_CT;
    int* src_tc  = I + I_SRC_TC;

    float* mean1_txn = F + F_MEAN1_TXN;
    float* mean1_cli = F + F_MEAN1_CLI;
    float* h_txn     = F + F_H_TXN;
    float* h_cli     = F + F_H_CLI;
    float* pre       = F + F_PRE;
    float* mean2_txn = F + F_MEAN2_TXN;
    float* mean2_cli = F + F_MEAN2_CLI;
    float* dec       = F + F_DEC;

    const int TB = 256;
    const int eblocks = (N_E + TB - 1) / TB;

    // CSR build (shared by both layers)
    zero_cnt_kernel<<<(N_TXN + TB - 1) / TB, TB>>>(cnt_txn, cnt_cli);
    count_kernel<<<eblocks, TB>>>(ct_dst, tc_dst, cnt_txn, cnt_cli);
    scan_kernel<<<1, 1024>>>(cnt_txn, off_txn, cur_txn, cnt_cli, off_cli, cur_cli);
    fill_kernel<<<eblocks, TB>>>(ct_src, ct_dst, tc_src, tc_dst,
                                 cur_txn, cur_cli, src_ct, src_tc);

    // Layer 1 aggregation (gather-side mean)
    mean_gather_kernel<32><<<(N_TXN * 32 + TB - 1) / TB, TB>>>(
        x_cli, src_ct, off_txn, cnt_txn, mean1_txn, N_TXN);
    mean_gather_kernel<64><<<(N_CLI * 32 + TB - 1) / TB, TB>>>(
        x_txn, src_tc, off_cli, cnt_cli, mean1_cli, N_CLI);

    // Layer 1 dual GEMM + bias + ReLU
    gemm_kernel<32, 64, 128, true, false><<<(N_TXN + 63) / 64, 256>>>(
        mean1_txn, W1_ct_l, x_txn, W1_ct_r, b1_ct, nullptr, h_txn, N_TXN);
    gemm_kernel<64, 32, 128, true, false><<<(N_CLI + 63) / 64, 256>>>(
        mean1_cli, W1_tc_l, x_cli, W1_tc_r, b1_tc, nullptr, h_cli, N_CLI);

    // Layer 2: pre-multiply h_cli by W2_ct_l (linearity of mean), then aggregate
    gemm_kernel<128, 0, 128, false, false><<<(N_CLI + 63) / 64, 256>>>(
        h_cli, W2_ct_l, nullptr, nullptr, nullptr, nullptr, pre, N_CLI);
    mean_gather_kernel<128><<<(N_TXN * 32 + TB - 1) / TB, TB>>>(
        pre, src_ct, off_txn, cnt_txn, mean2_txn, N_TXN);
    mean_gather_kernel<128><<<(N_CLI * 32 + TB - 1) / TB, TB>>>(
        h_txn, src_tc, off_cli, cnt_cli, mean2_cli, N_CLI);

    // z_txn = h_txn @ W2_ct_r + mean2_txn + b2_ct      (into d_out)
    gemm_kernel<128, 0, 128, false, true><<<(N_TXN + 63) / 64, 256>>>(
        h_txn, W2_ct_r, nullptr, nullptr, b2_ct, mean2_txn, z_txn, N_TXN);
    // z_cli = mean2_cli @ W2_tc_l + h_cli @ W2_tc_r + b2_tc   (into d_out)
    gemm_kernel<128, 128, 128, false, false><<<(N_CLI + 63) / 64, 256>>>(
        mean2_cli, W2_tc_l, h_cli, W2_tc_r, b2_tc, nullptr, z_cli, N_CLI);

    // Decoder
    gemm_kernel<128, 0, 64, true, false><<<(N_TXN + 63) / 64, 256>>>(
        z_txn, Wd1, nullptr, nullptr, bd1, nullptr, dec, N_TXN);
    gemm_kernel<64, 0, 64, false, false><<<(N_TXN + 63) / 64, 256>>>(
        dec, Wd2, nullptr, nullptr, bd2, nullptr, recon, N_TXN);
}

// round 2
// speedup vs baseline: 1.2638x; 1.2638x over previous
#include <cuda_runtime.h>
#include <cstddef>

#define N_TXN 100000
#define N_CLI 20000
#define N_E   600000
#define N_TOT (N_TXN + N_CLI)
#define HDIM  128
#define SCAN_BLOCKS ((N_TOT + 1023) / 1024)

// ---------------- static scratch (no allocations allowed) ----------------
// int scratch layout (cnt_txn||cnt_cli contiguous for combined scan; same for off; src_ct||src_tc)
#define I_CNT_TXN 0
#define I_CNT_CLI (I_CNT_TXN + N_TXN)
#define I_OFF_TXN (I_CNT_CLI + N_CLI)
#define I_OFF_CLI (I_OFF_TXN + N_TXN)
#define I_SRC_CT  (I_OFF_CLI + N_CLI)
#define I_SRC_TC  (I_SRC_CT + N_E)
#define I_RANK_CT (I_SRC_TC + N_E)
#define I_RANK_TC (I_RANK_CT + N_E)
#define I_PART    (I_RANK_TC + N_E)
#define I_TOTAL   (I_PART + SCAN_BLOCKS + 8)

// float scratch layout
#define F_MEAN1_TXN 0                                        // N_TXN*32
#define F_MEAN1_CLI (F_MEAN1_TXN + (size_t)N_TXN*32)         // N_CLI*64
#define F_H_TXN     (F_MEAN1_CLI + (size_t)N_CLI*64)         // N_TXN*128
#define F_H_CLI     (F_H_TXN + (size_t)N_TXN*HDIM)           // N_CLI*128
#define F_PRE       (F_H_CLI + (size_t)N_CLI*HDIM)           // N_CLI*128
#define F_MEAN2_TXN (F_PRE + (size_t)N_CLI*HDIM)             // N_TXN*128
#define F_MEAN2_CLI (F_MEAN2_TXN + (size_t)N_TXN*HDIM)       // N_CLI*128
#define F_DEC       (F_MEAN2_CLI + (size_t)N_CLI*HDIM)       // N_TXN*64
#define F_TOTAL     (F_DEC + (size_t)N_TXN*64)

__device__ int   g_iscratch[I_TOTAL];
__device__ float g_fscratch[F_TOTAL];

// ---------------- CSR build ----------------
__global__ void zero_cnt_kernel(int* __restrict__ cnt_all) {
    int i = blockIdx.x * blockDim.x + threadIdx.x;
    if (i < N_TOT) cnt_all[i] = 0;
}

// count degrees AND record each edge's rank within its destination bucket
__global__ void count_kernel(const int* __restrict__ ct_dst, const int* __restrict__ tc_dst,
                             int* __restrict__ cnt_txn, int* __restrict__ cnt_cli,
                             int* __restrict__ rank_ct, int* __restrict__ rank_tc) {
    int e = blockIdx.x * blockDim.x + threadIdx.x;
    if (e < N_E) {
        rank_ct[e] = atomicAdd(&cnt_txn[ct_dst[e]], 1);
        rank_tc[e] = atomicAdd(&cnt_cli[tc_dst[e]], 1);
    }
}

// hierarchical exclusive scan over combined 120000-count array
__global__ __launch_bounds__(256) void scanA_kernel(const int* __restrict__ cnt,
                                                    int* __restrict__ off,
                                                    int* __restrict__ partials) {
    __shared__ int wsum[8];
    int tid = threadIdx.x, lane = tid & 31, wid = tid >> 5;
    int idx = blockIdx.x * 1024 + tid * 4;
    int4 v = make_int4(0, 0, 0, 0);
    if (idx + 3 < N_TOT) {
        v = *reinterpret_cast<const int4*>(cnt + idx);
    } else {
        if (idx + 0 < N_TOT) v.x = cnt[idx + 0];
        if (idx + 1 < N_TOT) v.y = cnt[idx + 1];
        if (idx + 2 < N_TOT) v.z = cnt[idx + 2];
        if (idx + 3 < N_TOT) v.w = cnt[idx + 3];
    }
    int t = v.x + v.y + v.z + v.w;
    int s = t;
#pragma unroll
    for (int d = 1; d < 32; d <<= 1) {
        int u = __shfl_up_sync(0xFFFFFFFFu, s, d);
        if (lane >= d) s += u;
    }
    if (lane == 31) wsum[wid] = s;
    __syncthreads();
    if (tid < 32) {
        int x = (tid < 8) ? wsum[tid] : 0;
        int ss = x;
#pragma unroll
        for (int d = 1; d < 8; d <<= 1) {
            int u = __shfl_up_sync(0xFFFFFFFFu, ss, d);
            if (lane >= d) ss += u;
        }
        if (tid < 8) wsum[tid] = ss - x;  // exclusive warp base
    }
    __syncthreads();
    int excl = wsum[wid] + s - t;
    int4 o;
    o.x = excl;
    o.y = excl + v.x;
    o.z = o.y + v.y;
    o.w = o.z + v.z;
    if (idx + 3 < N_TOT) {
        *reinterpret_cast<int4*>(off + idx) = o;
    } else {
        if (idx + 0 < N_TOT) off[idx + 0] = o.x;
        if (idx + 1 < N_TOT) off[idx + 1] = o.y;
        if (idx + 2 < N_TOT) off[idx + 2] = o.z;
        if (idx + 3 < N_TOT) off[idx + 3] = o.w;
    }
    if (tid == 255) partials[blockIdx.x] = excl + t;
}

__global__ __launch_bounds__(256) void scanC_kernel(const int* __restrict__ partials,
                                                    int* __restrict__ off) {
    __shared__ int red[8];
    __shared__ int sbase;
    int tid = threadIdx.x, lane = tid & 31, wid = tid >> 5;
    int blk = blockIdx.x;
    int acc = 0;
    for (int j = tid; j < blk; j += 256) acc += partials[j];
#pragma unroll
    for (int d = 16; d > 0; d >>= 1) acc += __shfl_down_sync(0xFFFFFFFFu, acc, d);
    if (lane == 0) red[wid] = acc;
    __syncthreads();
    if (tid == 0) {
        int b = 0;
#pragma unroll
        for (int w = 0; w < 8; w++) b += red[w];
        sbase = b;
    }
    __syncthreads();
    int b = sbase;
    if (b == 0) return;  // block 0 and any zero-base: nothing to add
    int idx = blk * 1024 + tid * 4;
    if (idx + 3 < N_TOT) {
        int4 o = *reinterpret_cast<int4*>(off + idx);
        o.x += b; o.y += b; o.z += b; o.w += b;
        *reinterpret_cast<int4*>(off + idx) = o;
    } else {
        for (int j = 0; j < 4; j++)
            if (idx + j < N_TOT) off[idx + j] += b;
    }
}

// atomic-free bucket fill using precomputed ranks; writes into combined src region
__global__ void fill_kernel(const int* __restrict__ ct_src, const int* __restrict__ ct_dst,
                            const int* __restrict__ tc_src, const int* __restrict__ tc_dst,
                            const int* __restrict__ rank_ct, const int* __restrict__ rank_tc,
                            const int* __restrict__ off_txn, const int* __restrict__ off_cli,
                            int* __restrict__ src_base) {
    int e = blockIdx.x * blockDim.x + threadIdx.x;
    if (e < N_E) {
        src_base[off_txn[ct_dst[e]] + rank_ct[e]] = ct_src[e];
        src_base[off_cli[tc_dst[e]] + rank_tc[e]] = tc_src[e];
    }
}

// ---------------- warp-per-node mean gather ----------------
template <int F>  // F in {32, 64, 128}
__global__ void mean_gather_kernel(const float* __restrict__ table,
                                   const int* __restrict__ srcs,
                                   const int* __restrict__ off,
                                   const int* __restrict__ cnt,
                                   float* __restrict__ out, int n) {
    int gw = (blockIdx.x * blockDim.x + threadIdx.x) >> 5;
    int lane = threadIdx.x & 31;
    int nw = (gridDim.x * blockDim.x) >> 5;
    for (int i = gw; i < n; i += nw) {
        int o = off[i], c = cnt[i];
        float inv = 1.0f / fmaxf((float)c, 1.0f);
        if (F == 128) {
            float4 acc = make_float4(0.f, 0.f, 0.f, 0.f);
            for (int e = 0; e < c; e++) {
                int s = __ldg(&srcs[o + e]);
                float4 v = *reinterpret_cast<const float4*>(table + (size_t)s * 128 + lane * 4);
                acc.x += v.x; acc.y += v.y; acc.z += v.z; acc.w += v.w;
            }
            acc.x *= inv; acc.y *= inv; acc.z *= inv; acc.w *= inv;
            *reinterpret_cast<float4*>(out + (size_t)i * 128 + lane * 4) = acc;
        } else if (F == 64) {
            float2 acc = make_float2(0.f, 0.f);
            for (int e = 0; e < c; e++) {
                int s = __ldg(&srcs[o + e]);
                float2 v = *reinterpret_cast<const float2*>(table + (size_t)s * 64 + lane * 2);
                acc.x += v.x; acc.y += v.y;
            }
            acc.x *= inv; acc.y *= inv;
            *reinterpret_cast<float2*>(out + (size_t)i * 64 + lane * 2) = acc;
        } else {
            float acc = 0.f;
            for (int e = 0; e < c; e++) {
                int s = __ldg(&srcs[o + e]);
                acc += table[(size_t)s * 32 + lane];
            }
            out[(size_t)i * 32 + lane] = acc * inv;
        }
    }
}

// ---------------- fused dual SGEMM with FFMA2 inner product ----------------
__device__ __forceinline__ unsigned long long pack_dup(float a) {
    unsigned long long r;
    unsigned int ai = __float_as_uint(a);
    asm("mov.b64 %0, {%1, %1};" : "=l"(r) : "r"(ai));
    return r;
}
__device__ __forceinline__ void ffma2(unsigned long long& acc, unsigned long long a,
                                      unsigned long long b) {
    asm("fma.rn.f32x2 %0, %1, %2, %0;" : "+l"(acc) : "l"(a), "l"(b));
}

// C[M x TN] = act( A1[M x K1] @ W1[K1 x TN] (+ A2 @ W2) (+ bias) (+ addend) )
template <int K1, int K2, int TN, bool RELU, bool HASADD>
__global__ __launch_bounds__(256) void gemm_kernel(
    const float* __restrict__ A1, const float* __restrict__ W1,
    const float* __restrict__ A2, const float* __restrict__ W2,
    const float* __restrict__ bias, const float* __restrict__ addend,
    float* __restrict__ C, int M) {
    constexpr int TM = 64, KC = 32, NR = TN / 16, NP = NR / 2;
    __shared__ float As[KC][TM + 4];   // transposed A tile (conflict-free LDS.128)
    __shared__ float Ws[KC][TN];
    const int tid = threadIdx.x;
    const int m0 = blockIdx.x * TM;
    const int rt = tid >> 4;   // 0..15 (row group of 4)
    const int ct = tid & 15;   // 0..15 (col group of NR)

    unsigned long long acc[4][NP];
#pragma unroll
    for (int i = 0; i < 4; i++)
#pragma unroll
        for (int j = 0; j < NP; j++) acc[i][j] = 0ull;

    auto run_piece = [&](const float* __restrict__ A, const float* __restrict__ W, int K) {
        for (int kc = 0; kc < K; kc += KC) {
            // load A tile [64 rows x 32 k] transposed into As[k][m]
            for (int i = tid; i < TM * KC / 4; i += 256) {
                int r = i >> 3, seg = i & 7;
                int m = m0 + r;
                float4 v = make_float4(0.f, 0.f, 0.f, 0.f);
                if (m < M) v = *reinterpret_cast<const float4*>(A + (size_t)m * K + kc + seg * 4);
                As[seg * 4 + 0][r] = v.x;
                As[seg * 4 + 1][r] = v.y;
                As[seg * 4 + 2][r] = v.z;
                As[seg * 4 + 3][r] = v.w;
            }
            // load W tile [32 x TN]
            for (int i = tid; i < KC * TN / 4; i += 256) {
                int k = i / (TN / 4), c = i % (TN / 4);
                *reinterpret_cast<float4*>(&Ws[k][c * 4]) =
                    *reinterpret_cast<const float4*>(W + (size_t)(kc + k) * TN + c * 4);
            }
            __syncthreads();
#pragma unroll 8
            for (int k = 0; k < KC; k++) {
                float4 av = *reinterpret_cast<const float4*>(&As[k][rt * 4]);
                unsigned long long a2[4];
                a2[0] = pack_dup(av.x);
                a2[1] = pack_dup(av.y);
                a2[2] = pack_dup(av.z);
                a2[3] = pack_dup(av.w);
                unsigned long long w[NP];
                if (NP == 4) {
                    ulonglong2 w01 = *reinterpret_cast<const ulonglong2*>(&Ws[k][ct * NR]);
                    ulonglong2 w23 = *reinterpret_cast<const ulonglong2*>(&Ws[k][ct * NR + 4]);
                    w[0] = w01.x; w[1] = w01.y; w[2] = w23.x; w[3] = w23.y;
                } else {
                    ulonglong2 w01 = *reinterpret_cast<const ulonglong2*>(&Ws[k][ct * NR]);
                    w[0] = w01.x; w[1] = w01.y;
                }
#pragma unroll
                for (int i = 0; i < 4; i++)
#pragma unroll
                    for (int j = 0; j < NP; j++) ffma2(acc[i][j], a2[i], w[j]);
            }
            __syncthreads();
        }
    };

    run_piece(A1, W1, K1);
    if (K2 > 0) run_piece(A2, W2, K2);

    // epilogue
#pragma unroll
    for (int i = 0; i < 4; i++) {
        int m = m0 + rt * 4 + i;
        if (m >= M) continue;
        float v[NR];
#pragma unroll
        for (int j = 0; j < NP; j++) {
            float2 p = *reinterpret_cast<const float2*>(&acc[i][j]);
            v[j * 2 + 0] = p.x;
            v[j * 2 + 1] = p.y;
        }
#pragma unroll
        for (int j = 0; j < NR; j++) {
            float x = v[j];
            if (bias) x += bias[ct * NR + j];
            if (HASADD) x += addend[(size_t)m * TN + ct * NR + j];
            if (RELU) x = fmaxf(x, 0.f);
            v[j] = x;
        }
#pragma unroll
        for (int j = 0; j < NR; j += 4)
            *reinterpret_cast<float4*>(C + (size_t)m * TN + ct * NR + j) =
                *reinterpret_cast<const float4*>(&v[j]);
    }
}

// ---------------- launch ----------------
extern "C" void kernel_launch(void* const* d_in, const int* in_sizes, int n_in,
                              void* d_out, int out_size) {
    const float* x_txn   = (const float*)d_in[0];
    const float* x_cli   = (const float*)d_in[1];
    const int*   ct_src  = (const int*)d_in[2];
    const int*   ct_dst  = (const int*)d_in[3];
    const int*   tc_src  = (const int*)d_in[4];
    const int*   tc_dst  = (const int*)d_in[5];
    const float* W1_ct_l = (const float*)d_in[6];
    const float* b1_ct   = (const float*)d_in[7];
    const float* W1_ct_r = (const float*)d_in[8];
    const float* W1_tc_l = (const float*)d_in[9];
    const float* b1_tc   = (const float*)d_in[10];
    const float* W1_tc_r = (const float*)d_in[11];
    const float* W2_ct_l = (const float*)d_in[12];
    const float* b2_ct   = (const float*)d_in[13];
    const float* W2_ct_r = (const float*)d_in[14];
    const float* W2_tc_l = (const float*)d_in[15];
    const float* b2_tc   = (const float*)d_in[16];
    const float* W2_tc_r = (const float*)d_in[17];
    const float* Wd1     = (const float*)d_in[18];
    const float* bd1     = (const float*)d_in[19];
    const float* Wd2     = (const float*)d_in[20];
    const float* bd2     = (const float*)d_in[21];

    float* out = (float*)d_out;
    float* recon = out;                                  // [N_TXN x 64]
    float* z_txn = out + (size_t)N_TXN * 64;             // [N_TXN x 128]
    float* z_cli = z_txn + (size_t)N_TXN * 128;          // [N_CLI x 128]

    void* p = nullptr;
    cudaGetSymbolAddress(&p, g_iscratch);
    int* I = (int*)p;
    cudaGetSymbolAddress(&p, g_fscratch);
    float* F = (float*)p;

    int* cnt_all  = I + I_CNT_TXN;   // combined [N_TOT]
    int* cnt_txn  = I + I_CNT_TXN;
    int* cnt_cli  = I + I_CNT_CLI;
    int* off_all  = I + I_OFF_TXN;   // combined [N_TOT]
    int* off_txn  = I + I_OFF_TXN;
    int* off_cli  = I + I_OFF_CLI;
    int* src_base = I + I_SRC_CT;    // combined [2*N_E]
    int* rank_ct  = I + I_RANK_CT;
    int* rank_tc  = I + I_RANK_TC;
    int* partials = I + I_PART;

    float* mean1_txn = F + F_MEAN1_TXN;
    float* mean1_cli = F + F_MEAN1_CLI;
    float* h_txn     = F + F_H_TXN;
    float* h_cli     = F + F_H_CLI;
    float* pre       = F + F_PRE;
    float* mean2_txn = F + F_MEAN2_TXN;
    float* mean2_cli = F + F_MEAN2_CLI;
    float* dec       = F + F_DEC;

    const int TB = 256;
    const int eblocks = (N_E + TB - 1) / TB;

    // CSR build (shared by both layers) — hierarchical scan, atomic-free fill
    zero_cnt_kernel<<<(N_TOT + TB - 1) / TB, TB>>>(cnt_all);
    count_kernel<<<eblocks, TB>>>(ct_dst, tc_dst, cnt_txn, cnt_cli, rank_ct, rank_tc);
    scanA_kernel<<<SCAN_BLOCKS, 256>>>(cnt_all, off_all, partials);
    scanC_kernel<<<SCAN_BLOCKS, 256>>>(partials, off_all);
    fill_kernel<<<eblocks, TB>>>(ct_src, ct_dst, tc_src, tc_dst,
                                 rank_ct, rank_tc, off_txn, off_cli, src_base);

    // Layer 1 aggregation (gather-side mean)
    mean_gather_kernel<32><<<(N_TXN * 32 + TB - 1) / TB, TB>>>(
        x_cli, src_base, off_txn, cnt_txn, mean1_txn, N_TXN);
    mean_gather_kernel<64><<<(N_CLI * 32 + TB - 1) / TB, TB>>>(
        x_txn, src_base, off_cli, cnt_cli, mean1_cli, N_CLI);

    // Layer 1 dual GEMM + bias + ReLU
    gemm_kernel<32, 64, 128, true, false><<<(N_TXN + 63) / 64, 256>>>(
        mean1_txn, W1_ct_l, x_txn, W1_ct_r, b1_ct, nullptr, h_txn, N_TXN);
    gemm_kernel<64, 32, 128, true, false><<<(N_CLI + 63) / 64, 256>>>(
        mean1_cli, W1_tc_l, x_cli, W1_tc_r, b1_tc, nullptr, h_cli, N_CLI);

    // Layer 2: pre-multiply h_cli by W2_ct_l (linearity of mean), then aggregate
    gemm_kernel<128, 0, 128, false, false><<<(N_CLI + 63) / 64, 256>>>(
        h_cli, W2_ct_l, nullptr, nullptr, nullptr, nullptr, pre, N_CLI);
    mean_gather_kernel<128><<<(N_TXN * 32 + TB - 1) / TB, TB>>>(
        pre, src_base, off_txn, cnt_txn, mean2_txn, N_TXN);
    mean_gather_kernel<128><<<(N_CLI * 32 + TB - 1) / TB, TB>>>(
        h_txn, src_base, off_cli, cnt_cli, mean2_cli, N_CLI);

    // z_txn = h_txn @ W2_ct_r + mean2_txn + b2_ct      (into d_out)
    gemm_kernel<128, 0, 128, false, true><<<(N_TXN + 63) / 64, 256>>>(
        h_txn, W2_ct_r, nullptr, nullptr, b2_ct, mean2_txn, z_txn, N_TXN);
    // z_cli = mean2_cli @ W2_tc_l + h_cli @ W2_tc_r + b2_tc   (into d_out)
    gemm_kernel<128, 128, 128, false, false><<<(N_CLI + 63) / 64, 256>>>(
        mean2_cli, W2_tc_l, h_cli, W2_tc_r, b2_tc, nullptr, z_cli, N_CLI);

    // Decoder
    gemm_kernel<128, 0, 64, true, false><<<(N_TXN + 63) / 64, 256>>>(
        z_txn, Wd1, nullptr, nullptr, bd1, nullptr, dec, N_TXN);
    gemm_kernel<64, 0, 64, false, false><<<(N_TXN + 63) / 64, 256>>>(
        dec, Wd2, nullptr, nullptr, bd2, nullptr, recon, N_TXN);
}

// round 3
// speedup vs baseline: 1.5365x; 1.2158x over previous
#include <cuda_runtime.h>
#include <cstddef>

#define N_TXN 100000
#define N_CLI 20000
#define N_E   600000
#define N_TOT (N_TXN + N_CLI)
#define HDIM  128
#define SCAN_BLOCKS ((N_TOT + 1023) / 1024)

// ---------------- static scratch ----------------
#define I_CNT_TXN 0
#define I_CNT_CLI (I_CNT_TXN + N_TXN)
#define I_OFF_TXN (I_CNT_CLI + N_CLI)
#define I_OFF_CLI (I_OFF_TXN + N_TXN)
#define I_SRC_CT  (I_OFF_CLI + N_CLI)
#define I_SRC_TC  (I_SRC_CT + N_E)
#define I_RANK_CT (I_SRC_TC + N_E)
#define I_RANK_TC (I_RANK_CT + N_E)
#define I_PART    (I_RANK_TC + N_E)
#define I_TOTAL   (I_PART + SCAN_BLOCKS + 8)

#define F_MEAN1_TXN 0
#define F_MEAN1_CLI (F_MEAN1_TXN + (size_t)N_TXN*32)
#define F_H_TXN     (F_MEAN1_CLI + (size_t)N_CLI*64)
#define F_H_CLI     (F_H_TXN + (size_t)N_TXN*HDIM)
#define F_PRE       (F_H_CLI + (size_t)N_CLI*HDIM)
#define F_MEAN2_TXN (F_PRE + (size_t)N_CLI*HDIM)
#define F_MEAN2_CLI (F_MEAN2_TXN + (size_t)N_TXN*HDIM)
#define F_DEC       (F_MEAN2_CLI + (size_t)N_CLI*HDIM)
#define F_TOTAL     (F_DEC + (size_t)N_TXN*64)

__device__ int   g_iscratch[I_TOTAL];
__device__ float g_fscratch[F_TOTAL];

// ---------------- CSR build ----------------
__global__ void zero_cnt_kernel(int* __restrict__ cnt_all) {
    int i = blockIdx.x * blockDim.x + threadIdx.x;
    if (i < N_TOT) cnt_all[i] = 0;
}

__global__ void count_kernel(const int* __restrict__ ct_dst, const int* __restrict__ tc_dst,
                             int* __restrict__ cnt_txn, int* __restrict__ cnt_cli,
                             int* __restrict__ rank_ct, int* __restrict__ rank_tc) {
    int e = blockIdx.x * blockDim.x + threadIdx.x;
    if (e < N_E) {
        rank_ct[e] = atomicAdd(&cnt_txn[ct_dst[e]], 1);
        rank_tc[e] = atomicAdd(&cnt_cli[tc_dst[e]], 1);
    }
}

__global__ __launch_bounds__(256) void scanA_kernel(const int* __restrict__ cnt,
                                                    int* __restrict__ off,
                                                    int* __restrict__ partials) {
    __shared__ int wsum[8];
    int tid = threadIdx.x, lane = tid & 31, wid = tid >> 5;
    int idx = blockIdx.x * 1024 + tid * 4;
    int4 v = make_int4(0, 0, 0, 0);
    if (idx + 3 < N_TOT) {
        v = *reinterpret_cast<const int4*>(cnt + idx);
    } else {
        if (idx + 0 < N_TOT) v.x = cnt[idx + 0];
        if (idx + 1 < N_TOT) v.y = cnt[idx + 1];
        if (idx + 2 < N_TOT) v.z = cnt[idx + 2];
        if (idx + 3 < N_TOT) v.w = cnt[idx + 3];
    }
    int t = v.x + v.y + v.z + v.w;
    int s = t;
#pragma unroll
    for (int d = 1; d < 32; d <<= 1) {
        int u = __shfl_up_sync(0xFFFFFFFFu, s, d);
        if (lane >= d) s += u;
    }
    if (lane == 31) wsum[wid] = s;
    __syncthreads();
    if (tid < 32) {
        int x = (tid < 8) ? wsum[tid] : 0;
        int ss = x;
#pragma unroll
        for (int d = 1; d < 8; d <<= 1) {
            int u = __shfl_up_sync(0xFFFFFFFFu, ss, d);
            if (lane >= d) ss += u;
        }
        if (tid < 8) wsum[tid] = ss - x;
    }
    __syncthreads();
    int excl = wsum[wid] + s - t;
    int4 o;
    o.x = excl;
    o.y = excl + v.x;
    o.z = o.y + v.y;
    o.w = o.z + v.z;
    if (idx + 3 < N_TOT) {
        *reinterpret_cast<int4*>(off + idx) = o;
    } else {
        if (idx + 0 < N_TOT) off[idx + 0] = o.x;
        if (idx + 1 < N_TOT) off[idx + 1] = o.y;
        if (idx + 2 < N_TOT) off[idx + 2] = o.z;
        if (idx + 3 < N_TOT) off[idx + 3] = o.w;
    }
    if (tid == 255) partials[blockIdx.x] = excl + t;
}

__global__ __launch_bounds__(256) void scanC_kernel(const int* __restrict__ partials,
                                                    int* __restrict__ off) {
    __shared__ int red[8];
    __shared__ int sbase;
    int tid = threadIdx.x, lane = tid & 31, wid = tid >> 5;
    int blk = blockIdx.x;
    int acc = 0;
    for (int j = tid; j < blk; j += 256) acc += partials[j];
#pragma unroll
    for (int d = 16; d > 0; d >>= 1) acc += __shfl_down_sync(0xFFFFFFFFu, acc, d);
    if (lane == 0) red[wid] = acc;
    __syncthreads();
    if (tid == 0) {
        int b = 0;
#pragma unroll
        for (int w = 0; w < 8; w++) b += red[w];
        sbase = b;
    }
    __syncthreads();
    int b = sbase;
    if (b == 0) return;
    int idx = blk * 1024 + tid * 4;
    if (idx + 3 < N_TOT) {
        int4 o = *reinterpret_cast<int4*>(off + idx);
        o.x += b; o.y += b; o.z += b; o.w += b;
        *reinterpret_cast<int4*>(off + idx) = o;
    } else {
        for (int j = 0; j < 4; j++)
            if (idx + j < N_TOT) off[idx + j] += b;
    }
}

__global__ void fill_kernel(const int* __restrict__ ct_src, const int* __restrict__ ct_dst,
                            const int* __restrict__ tc_src, const int* __restrict__ tc_dst,
                            const int* __restrict__ rank_ct, const int* __restrict__ rank_tc,
                            const int* __restrict__ off_txn, const int* __restrict__ off_cli,
                            int* __restrict__ src_base) {
    int e = blockIdx.x * blockDim.x + threadIdx.x;
    if (e < N_E) {
        src_base[off_txn[ct_dst[e]] + rank_ct[e]] = ct_src[e];
        src_base[off_cli[tc_dst[e]] + rank_tc[e]] = tc_src[e];
    }
}

// ---------------- warp-per-node mean gather ----------------
template <int F>
__global__ void mean_gather_kernel(const float* __restrict__ table,
                                   const int* __restrict__ srcs,
                                   const int* __restrict__ off,
                                   const int* __restrict__ cnt,
                                   float* __restrict__ out, int n) {
    int gw = (blockIdx.x * blockDim.x + threadIdx.x) >> 5;
    int lane = threadIdx.x & 31;
    int nw = (gridDim.x * blockDim.x) >> 5;
    for (int i = gw; i < n; i += nw) {
        int o = off[i], c = cnt[i];
        float inv = 1.0f / fmaxf((float)c, 1.0f);
        if (F == 128) {
            float4 acc = make_float4(0.f, 0.f, 0.f, 0.f);
            for (int e = 0; e < c; e++) {
                int s = __ldg(&srcs[o + e]);
                float4 v = *reinterpret_cast<const float4*>(table + (size_t)s * 128 + lane * 4);
                acc.x += v.x; acc.y += v.y; acc.z += v.z; acc.w += v.w;
            }
            acc.x *= inv; acc.y *= inv; acc.z *= inv; acc.w *= inv;
            *reinterpret_cast<float4*>(out + (size_t)i * 128 + lane * 4) = acc;
        } else if (F == 64) {
            float2 acc = make_float2(0.f, 0.f);
            for (int e = 0; e < c; e++) {
                int s = __ldg(&srcs[o + e]);
                float2 v = *reinterpret_cast<const float2*>(table + (size_t)s * 64 + lane * 2);
                acc.x += v.x; acc.y += v.y;
            }
            acc.x *= inv; acc.y *= inv;
            *reinterpret_cast<float2*>(out + (size_t)i * 64 + lane * 2) = acc;
        } else {
            float acc = 0.f;
            for (int e = 0; e < c; e++) {
                int s = __ldg(&srcs[o + e]);
                acc += table[(size_t)s * 32 + lane];
            }
            out[(size_t)i * 32 + lane] = acc * inv;
        }
    }
}

// ---------------- 128xTN SGEMM, 8x8 micro-tile, FFMA2, double-buffered ----------------
__device__ __forceinline__ unsigned long long pack_dup(float a) {
    unsigned long long r;
    unsigned int ai = __float_as_uint(a);
    asm("mov.b64 %0, {%1, %1};" : "=l"(r) : "r"(ai));
    return r;
}
__device__ __forceinline__ void ffma2(unsigned long long& acc, unsigned long long a,
                                      unsigned long long b) {
    asm("fma.rn.f32x2 %0, %1, %2, %0;" : "+l"(acc) : "l"(a), "l"(b));
}

// C[M x TN] = act( A1 @ W1 (+ A2 @ W2) (+ bias) (+ addend) )
template <int K1, int K2, int TN, bool RELU, bool HASADD>
__global__ __launch_bounds__(256, 2) void gemm_kernel(
    const float* __restrict__ A1, const float* __restrict__ W1,
    const float* __restrict__ A2, const float* __restrict__ W2,
    const float* __restrict__ bias, const float* __restrict__ addend,
    float* __restrict__ C, int M) {
    constexpr int BM = 128, BK = 16;
    constexpr int NCOL = (TN == 128) ? 8 : 4;   // cols per thread (16x16 thread grid)
    constexpr int WF4 = TN / 64;                // W float4 loads per thread per tile (2 or 1)
    __shared__ float As[2][BK][BM + 4];
    __shared__ float Ws[2][BK][TN];

    const int tid = threadIdx.x;
    const int m0 = blockIdx.x * BM;
    const int rt = tid >> 4;   // 0..15, rows rt*8 .. rt*8+7
    const int ct = tid & 15;   // cols ct*NCOL ..

    // acc pairs along rows: acc[p][j] = (row 2p, row 2p+1) x col j
    unsigned long long acc[4][NCOL];
#pragma unroll
    for (int p = 0; p < 4; p++)
#pragma unroll
        for (int j = 0; j < NCOL; j++) acc[p][j] = 0ull;

    float4 aldg[2], wldg[2];

    auto ldg_tile = [&](const float* __restrict__ A, const float* __restrict__ W,
                        int K, int kc) {
#pragma unroll
        for (int rep = 0; rep < 2; rep++) {
            int idx = tid + rep * 256;          // 512 float4 of A tile
            int r = idx >> 2, c4 = idx & 3;
            int m = m0 + r;
            float4 v = make_float4(0.f, 0.f, 0.f, 0.f);
            if (m < M) v = *reinterpret_cast<const float4*>(A + (size_t)m * K + kc + c4 * 4);
            aldg[rep] = v;
        }
#pragma unroll
        for (int rep = 0; rep < WF4; rep++) {
            int idx = tid + rep * 256;          // BK*TN/4 float4 of W tile
            int k = idx / (TN / 4), c = idx % (TN / 4);
            wldg[rep] = *reinterpret_cast<const float4*>(W + (size_t)(kc + k) * TN + c * 4);
        }
    };
    auto sts_tile = [&](int buf) {
#pragma unroll
        for (int rep = 0; rep < 2; rep++) {
            int idx = tid + rep * 256;
            int r = idx >> 2, c4 = idx & 3;
            As[buf][c4 * 4 + 0][r] = aldg[rep].x;
            As[buf][c4 * 4 + 1][r] = aldg[rep].y;
            As[buf][c4 * 4 + 2][r] = aldg[rep].z;
            As[buf][c4 * 4 + 3][r] = aldg[rep].w;
        }
#pragma unroll
        for (int rep = 0; rep < WF4; rep++) {
            int idx = tid + rep * 256;
            int k = idx / (TN / 4), c = idx % (TN / 4);
            *reinterpret_cast<float4*>(&Ws[buf][k][c * 4]) = wldg[rep];
        }
    };
    auto compute = [&](int buf) {
#pragma unroll
        for (int k = 0; k < BK; k++) {
            // A fragment: 8 rows -> 4 natural f32x2 pairs
            ulonglong2 A01 = *reinterpret_cast<const ulonglong2*>(&As[buf][k][rt * 8]);
            ulonglong2 A23 = *reinterpret_cast<const ulonglong2*>(&As[buf][k][rt * 8 + 4]);
            unsigned long long ap[4] = {A01.x, A01.y, A23.x, A23.y};
            // W fragment: NCOL floats, duplicated into f32x2
            float wv[NCOL];
#pragma unroll
            for (int j = 0; j < NCOL; j += 4)
                *reinterpret_cast<float4*>(&wv[j]) =
                    *reinterpret_cast<const float4*>(&Ws[buf][k][ct * NCOL + j]);
            unsigned long long w2[NCOL];
#pragma unroll
            for (int j = 0; j < NCOL; j++) w2[j] = pack_dup(wv[j]);
#pragma unroll
            for (int p = 0; p < 4; p++)
#pragma unroll
                for (int j = 0; j < NCOL; j++) ffma2(acc[p][j], ap[p], w2[j]);
        }
    };
    auto run_piece = [&](const float* __restrict__ A, const float* __restrict__ W, int K) {
        const int nk = K / BK;
        ldg_tile(A, W, K, 0);
        sts_tile(0);
        __syncthreads();
        for (int t = 0; t < nk; t++) {
            if (t + 1 < nk) ldg_tile(A, W, K, (t + 1) * BK);
            compute(t & 1);
            if (t + 1 < nk) sts_tile((t + 1) & 1);
            __syncthreads();
        }
    };

    run_piece(A1, W1, K1);
    if (K2 > 0) run_piece(A2, W2, K2);

    // epilogue
    float bv[NCOL];
    if (bias) {
#pragma unroll
        for (int j = 0; j < NCOL; j++) bv[j] = bias[ct * NCOL + j];
    }
#pragma unroll
    for (int p = 0; p < 4; p++) {
        float r0[NCOL], r1[NCOL];
#pragma unroll
        for (int j = 0; j < NCOL; j++) {
            float2 pr = *reinterpret_cast<const float2*>(&acc[p][j]);
            r0[j] = pr.x;
            r1[j] = pr.y;
        }
        int m = m0 + rt * 8 + 2 * p;
#pragma unroll
        for (int half = 0; half < 2; half++) {
            int mm = m + half;
            if (mm >= M) continue;
            float* rr = half ? r1 : r0;
#pragma unroll
            for (int j = 0; j < NCOL; j++) {
                float x = rr[j];
                if (bias) x += bv[j];
                if (HASADD) x += addend[(size_t)mm * TN + ct * NCOL + j];
                if (RELU) x = fmaxf(x, 0.f);
                rr[j] = x;
            }
#pragma unroll
            for (int j = 0; j < NCOL; j += 4)
                *reinterpret_cast<float4*>(C + (size_t)mm * TN + ct * NCOL + j) =
                    *reinterpret_cast<const float4*>(&rr[j]);
        }
    }
}

// ---------------- launch ----------------
extern "C" void kernel_launch(void* const* d_in, const int* in_sizes, int n_in,
                              void* d_out, int out_size) {
    const float* x_txn   = (const float*)d_in[0];
    const float* x_cli   = (const float*)d_in[1];
    const int*   ct_src  = (const int*)d_in[2];
    const int*   ct_dst  = (const int*)d_in[3];
    const int*   tc_src  = (const int*)d_in[4];
    const int*   tc_dst  = (const int*)d_in[5];
    const float* W1_ct_l = (const float*)d_in[6];
    const float* b1_ct   = (const float*)d_in[7];
    const float* W1_ct_r = (const float*)d_in[8];
    const float* W1_tc_l = (const float*)d_in[9];
    const float* b1_tc   = (const float*)d_in[10];
    const float* W1_tc_r = (const float*)d_in[11];
    const float* W2_ct_l = (const float*)d_in[12];
    const float* b2_ct   = (const float*)d_in[13];
    const float* W2_ct_r = (const float*)d_in[14];
    const float* W2_tc_l = (const float*)d_in[15];
    const float* b2_tc   = (const float*)d_in[16];
    const float* W2_tc_r = (const float*)d_in[17];
    const float* Wd1     = (const float*)d_in[18];
    const float* bd1     = (const float*)d_in[19];
    const float* Wd2     = (const float*)d_in[20];
    const float* bd2     = (const float*)d_in[21];

    float* out = (float*)d_out;
    float* recon = out;
    float* z_txn = out + (size_t)N_TXN * 64;
    float* z_cli = z_txn + (size_t)N_TXN * 128;

    void* p = nullptr;
    cudaGetSymbolAddress(&p, g_iscratch);
    int* I = (int*)p;
    cudaGetSymbolAddress(&p, g_fscratch);
    float* F = (float*)p;

    int* cnt_all  = I + I_CNT_TXN;
    int* cnt_txn  = I + I_CNT_TXN;
    int* cnt_cli  = I + I_CNT_CLI;
    int* off_all  = I + I_OFF_TXN;
    int* off_txn  = I + I_OFF_TXN;
    int* off_cli  = I + I_OFF_CLI;
    int* src_base = I + I_SRC_CT;
    int* rank_ct  = I + I_RANK_CT;
    int* rank_tc  = I + I_RANK_TC;
    int* partials = I + I_PART;

    float* mean1_txn = F + F_MEAN1_TXN;
    float* mean1_cli = F + F_MEAN1_CLI;
    float* h_txn     = F + F_H_TXN;
    float* h_cli     = F + F_H_CLI;
    float* pre       = F + F_PRE;
    float* mean2_txn = F + F_MEAN2_TXN;
    float* mean2_cli = F + F_MEAN2_CLI;
    float* dec       = F + F_DEC;

    const int TB = 256;
    const int eblocks = (N_E + TB - 1) / TB;

    zero_cnt_kernel<<<(N_TOT + TB - 1) / TB, TB>>>(cnt_all);
    count_kernel<<<eblocks, TB>>>(ct_dst, tc_dst, cnt_txn, cnt_cli, rank_ct, rank_tc);
    scanA_kernel<<<SCAN_BLOCKS, 256>>>(cnt_all, off_all, partials);
    scanC_kernel<<<SCAN_BLOCKS, 256>>>(partials, off_all);
    fill_kernel<<<eblocks, TB>>>(ct_src, ct_dst, tc_src, tc_dst,
                                 rank_ct, rank_tc, off_txn, off_cli, src_base);

    mean_gather_kernel<32><<<(N_TXN * 32 + TB - 1) / TB, TB>>>(
        x_cli, src_base, off_txn, cnt_txn, mean1_txn, N_TXN);
    mean_gather_kernel<64><<<(N_CLI * 32 + TB - 1) / TB, TB>>>(
        x_txn, src_base, off_cli, cnt_cli, mean1_cli, N_CLI);

    gemm_kernel<32, 64, 128, true, false><<<(N_TXN + 127) / 128, 256>>>(
        mean1_txn, W1_ct_l, x_txn, W1_ct_r, b1_ct, nullptr, h_txn, N_TXN);
    gemm_kernel<64, 32, 128, true, false><<<(N_CLI + 127) / 128, 256>>>(
        mean1_cli, W1_tc_l, x_cli, W1_tc_r, b1_tc, nullptr, h_cli, N_CLI);

    gemm_kernel<128, 0, 128, false, false><<<(N_CLI + 127) / 128, 256>>>(
        h_cli, W2_ct_l, nullptr, nullptr, nullptr, nullptr, pre, N_CLI);
    mean_gather_kernel<128><<<(N_TXN * 32 + TB - 1) / TB, TB>>>(
        pre, src_base, off_txn, cnt_txn, mean2_txn, N_TXN);
    mean_gather_kernel<128><<<(N_CLI * 32 + TB - 1) / TB, TB>>>(
        h_txn, src_base, off_cli, cnt_cli, mean2_cli, N_CLI);

    gemm_kernel<128, 0, 128, false, true><<<(N_TXN + 127) / 128, 256>>>(
        h_txn, W2_ct_r, nullptr, nullptr, b2_ct, mean2_txn, z_txn, N_TXN);
    gemm_kernel<128, 128, 128, false, false><<<(N_CLI + 127) / 128, 256>>>(
        mean2_cli, W2_tc_l, h_cli, W2_tc_r, b2_tc, nullptr, z_cli, N_CLI);

    gemm_kernel<128, 0, 64, true, false><<<(N_TXN + 127) / 128, 256>>>(
        z_txn, Wd1, nullptr, nullptr, bd1, nullptr, dec, N_TXN);
    gemm_kernel<64, 0, 64, false, false><<<(N_TXN + 127) / 128, 256>>>(
        dec, Wd2, nullptr, nullptr, bd2, nullptr, recon, N_TXN);
}

// round 5
// speedup vs baseline: 2.1534x; 1.4015x over previous
#include <cuda_runtime.h>
#include <cuda_bf16.h>
#include <cstdint>
#include <cstddef>

#define N_TXN 100000
#define N_CLI 20000
#define N_E   600000
#define N_TOT (N_TXN + N_CLI)
#define HDIM  128
#define SCAN_BLOCKS ((N_TOT + 1023) / 1024)

// ---------------- static scratch ----------------
#define I_CNT_TXN 0
#define I_CNT_CLI (I_CNT_TXN + N_TXN)
#define I_OFF_TXN (I_CNT_CLI + N_CLI)
#define I_OFF_CLI (I_OFF_TXN + N_TXN)
#define I_SRC_CT  (I_OFF_CLI + N_CLI)
#define I_SRC_TC  (I_SRC_CT + N_E)
#define I_RANK_CT (I_SRC_TC + N_E)
#define I_RANK_TC (I_RANK_CT + N_E)
#define I_PART    (I_RANK_TC + N_E)
#define I_TOTAL   (I_PART + SCAN_BLOCKS + 8)

#define F_MEAN1_TXN 0
#define F_MEAN1_CLI (F_MEAN1_TXN + (size_t)N_TXN*32)
#define F_H_TXN     (F_MEAN1_CLI + (size_t)N_CLI*64)
#define F_H_CLI     (F_H_TXN + (size_t)N_TXN*HDIM)
#define F_PRE       (F_H_CLI + (size_t)N_CLI*HDIM)
#define F_MEAN2_TXN (F_PRE + (size_t)N_CLI*HDIM)
#define F_MEAN2_CLI (F_MEAN2_TXN + (size_t)N_TXN*HDIM)
#define F_DEC       (F_MEAN2_CLI + (size_t)N_CLI*HDIM)
#define F_TOTAL     (F_DEC + (size_t)N_TXN*64)

__device__ int   g_iscratch[I_TOTAL];
__device__ float g_fscratch[F_TOTAL];

// ---------------- CSR build ----------------
__global__ void zero_cnt_kernel(int* __restrict__ cnt_all) {
    int i = blockIdx.x * blockDim.x + threadIdx.x;
    if (i < N_TOT) cnt_all[i] = 0;
}

__global__ void count_kernel(const int* __restrict__ ct_dst, const int* __restrict__ tc_dst,
                             int* __restrict__ cnt_txn, int* __restrict__ cnt_cli,
                             int* __restrict__ rank_ct, int* __restrict__ rank_tc) {
    int e = blockIdx.x * blockDim.x + threadIdx.x;
    if (e < N_E) {
        rank_ct[e] = atomicAdd(&cnt_txn[ct_dst[e]], 1);
        rank_tc[e] = atomicAdd(&cnt_cli[tc_dst[e]], 1);
    }
}

__global__ __launch_bounds__(256) void scanA_kernel(const int* __restrict__ cnt,
                                                    int* __restrict__ off,
                                                    int* __restrict__ partials) {
    __shared__ int wsum[8];
    int tid = threadIdx.x, lane = tid & 31, wid = tid >> 5;
    int idx = blockIdx.x * 1024 + tid * 4;
    int4 v = make_int4(0, 0, 0, 0);
    if (idx + 3 < N_TOT) {
        v = *reinterpret_cast<const int4*>(cnt + idx);
    } else {
        if (idx + 0 < N_TOT) v.x = cnt[idx + 0];
        if (idx + 1 < N_TOT) v.y = cnt[idx + 1];
        if (idx + 2 < N_TOT) v.z = cnt[idx + 2];
        if (idx + 3 < N_TOT) v.w = cnt[idx + 3];
    }
    int t = v.x + v.y + v.z + v.w;
    int s = t;
#pragma unroll
    for (int d = 1; d < 32; d <<= 1) {
        int u = __shfl_up_sync(0xFFFFFFFFu, s, d);
        if (lane >= d) s += u;
    }
    if (lane == 31) wsum[wid] = s;
    __syncthreads();
    if (tid < 32) {
        int x = (tid < 8) ? wsum[tid] : 0;
        int ss = x;
#pragma unroll
        for (int d = 1; d < 8; d <<= 1) {
            int u = __shfl_up_sync(0xFFFFFFFFu, ss, d);
            if (lane >= d) ss += u;
        }
        if (tid < 8) wsum[tid] = ss - x;
    }
    __syncthreads();
    int excl = wsum[wid] + s - t;
    int4 o;
    o.x = excl;
    o.y = excl + v.x;
    o.z = o.y + v.y;
    o.w = o.z + v.z;
    if (idx + 3 < N_TOT) {
        *reinterpret_cast<int4*>(off + idx) = o;
    } else {
        if (idx + 0 < N_TOT) off[idx + 0] = o.x;
        if (idx + 1 < N_TOT) off[idx + 1] = o.y;
        if (idx + 2 < N_TOT) off[idx + 2] = o.z;
        if (idx + 3 < N_TOT) off[idx + 3] = o.w;
    }
    if (tid == 255) partials[blockIdx.x] = excl + t;
}

__global__ __launch_bounds__(256) void scanC_kernel(const int* __restrict__ partials,
                                                    int* __restrict__ off) {
    __shared__ int red[8];
    __shared__ int sbase;
    int tid = threadIdx.x, lane = tid & 31, wid = tid >> 5;
    int blk = blockIdx.x;
    int acc = 0;
    for (int j = tid; j < blk; j += 256) acc += partials[j];
#pragma unroll
    for (int d = 16; d > 0; d >>= 1) acc += __shfl_down_sync(0xFFFFFFFFu, acc, d);
    if (lane == 0) red[wid] = acc;
    __syncthreads();
    if (tid == 0) {
        int b = 0;
#pragma unroll
        for (int w = 0; w < 8; w++) b += red[w];
        sbase = b;
    }
    __syncthreads();
    int b = sbase;
    if (b == 0) return;
    int idx = blk * 1024 + tid * 4;
    if (idx + 3 < N_TOT) {
        int4 o = *reinterpret_cast<int4*>(off + idx);
        o.x += b; o.y += b; o.z += b; o.w += b;
        *reinterpret_cast<int4*>(off + idx) = o;
    } else {
        for (int j = 0; j < 4; j++)
            if (idx + j < N_TOT) off[idx + j] += b;
    }
}

__global__ void fill_kernel(const int* __restrict__ ct_src, const int* __restrict__ ct_dst,
                            const int* __restrict__ tc_src, const int* __restrict__ tc_dst,
                            const int* __restrict__ rank_ct, const int* __restrict__ rank_tc,
                            const int* __restrict__ off_txn, const int* __restrict__ off_cli,
                            int* __restrict__ src_base) {
    int e = blockIdx.x * blockDim.x + threadIdx.x;
    if (e < N_E) {
        src_base[off_txn[ct_dst[e]] + rank_ct[e]] = ct_src[e];
        src_base[off_cli[tc_dst[e]] + rank_tc[e]] = tc_src[e];
    }
}

// ---------------- warp-per-node mean gather ----------------
template <int F>
__global__ void mean_gather_kernel(const float* __restrict__ table,
                                   const int* __restrict__ srcs,
                                   const int* __restrict__ off,
                                   const int* __restrict__ cnt,
                                   float* __restrict__ out, int n) {
    int gw = (blockIdx.x * blockDim.x + threadIdx.x) >> 5;
    int lane = threadIdx.x & 31;
    int nw = (gridDim.x * blockDim.x) >> 5;
    for (int i = gw; i < n; i += nw) {
        int o = off[i], c = cnt[i];
        float inv = 1.0f / fmaxf((float)c, 1.0f);
        if (F == 128) {
            float4 acc = make_float4(0.f, 0.f, 0.f, 0.f);
            for (int e = 0; e < c; e++) {
                int s = __ldg(&srcs[o + e]);
                float4 v = *reinterpret_cast<const float4*>(table + (size_t)s * 128 + lane * 4);
                acc.x += v.x; acc.y += v.y; acc.z += v.z; acc.w += v.w;
            }
            acc.x *= inv; acc.y *= inv; acc.z *= inv; acc.w *= inv;
            *reinterpret_cast<float4*>(out + (size_t)i * 128 + lane * 4) = acc;
        } else if (F == 64) {
            float2 acc = make_float2(0.f, 0.f);
            for (int e = 0; e < c; e++) {
                int s = __ldg(&srcs[o + e]);
                float2 v = *reinterpret_cast<const float2*>(table + (size_t)s * 64 + lane * 2);
                acc.x += v.x; acc.y += v.y;
            }
            acc.x *= inv; acc.y *= inv;
            *reinterpret_cast<float2*>(out + (size_t)i * 64 + lane * 2) = acc;
        } else {
            float acc = 0.f;
            for (int e = 0; e < c; e++) {
                int s = __ldg(&srcs[o + e]);
                acc += table[(size_t)s * 32 + lane];
            }
            out[(size_t)i * 32 + lane] = acc * inv;
        }
    }
}

// ---------------- tensor-core SGEMM via bf16-split mma.sync ----------------
__device__ __forceinline__ uint32_t smem_u32(const void* p) {
    return (uint32_t)__cvta_generic_to_shared(p);
}
__device__ __forceinline__ void ldsm_x4(uint32_t* r, uint32_t addr) {
    asm volatile("ldmatrix.sync.aligned.m8n8.x4.shared.b16 {%0,%1,%2,%3}, [%4];"
                 : "=r"(r[0]), "=r"(r[1]), "=r"(r[2]), "=r"(r[3]) : "r"(addr));
}
__device__ __forceinline__ void ldsm_x4_t(uint32_t* r, uint32_t addr) {
    asm volatile("ldmatrix.sync.aligned.m8n8.x4.trans.shared.b16 {%0,%1,%2,%3}, [%4];"
                 : "=r"(r[0]), "=r"(r[1]), "=r"(r[2]), "=r"(r[3]) : "r"(addr));
}
__device__ __forceinline__ void mma16816(float* c, const uint32_t* a, const uint32_t* b) {
    asm volatile(
        "mma.sync.aligned.m16n8k16.row.col.f32.bf16.bf16.f32 "
        "{%0,%1,%2,%3}, {%4,%5,%6,%7}, {%8,%9}, {%0,%1,%2,%3};"
        : "+f"(c[0]), "+f"(c[1]), "+f"(c[2]), "+f"(c[3])
        : "r"(a[0]), "r"(a[1]), "r"(a[2]), "r"(a[3]), "r"(b[0]), "r"(b[1]));
}
__device__ __forceinline__ void split4(const float4& v, __nv_bfloat16* hi, __nv_bfloat16* lo) {
    const float* f = (const float*)&v;
#pragma unroll
    for (int i = 0; i < 4; i++) {
        __nv_bfloat16 h = __float2bfloat16_rn(f[i]);
        hi[i] = h;
        lo[i] = __float2bfloat16_rn(f[i] - __bfloat162float(h));
    }
}

// C[M x TN] = act( A1 @ W1 (+ A2 @ W2) (+ bias) (+ addend) ), fp32 in/out
// Warp grid: TN=128 -> 2x4 warps (warp tile 64x32); TN=64 -> 4x2 warps (32x32).
template <int K1, int K2, int TN, bool RELU, bool HASADD>
__global__ __launch_bounds__(256, 1) void gemm_kernel(
    const float* __restrict__ A1, const float* __restrict__ W1,
    const float* __restrict__ A2, const float* __restrict__ W2,
    const float* __restrict__ bias, const float* __restrict__ addend,
    float* __restrict__ C, int M) {
    constexpr int BM = 128, BK = 16;
    constexpr int TNP = TN + 8;
    constexpr int WF4 = (TN == 128) ? 2 : 1;
    constexpr int WC = (TN == 128) ? 4 : 2;   // warp cols (x32 each)
    constexpr int MI = (TN == 128) ? 4 : 2;   // m16 tiles per warp
    __shared__ __align__(16) __nv_bfloat16 As[2][2][BM][24];   // [buf][plane][m][k+pad]
    __shared__ __align__(16) __nv_bfloat16 Ws[2][2][BK][TNP];  // [buf][plane][k][n+pad]

    const int tid = threadIdx.x;
    const int lane = tid & 31, wid = tid >> 5;
    const int m0 = blockIdx.x * BM;
    const int mw = (wid / WC) * (MI * 16);  // warp row origin
    const int nw = (wid % WC) * 32;         // warp col origin
    const int lrow = lane & 15, lhalf = lane >> 4;  // ldmatrix lane addressing
    const int g = lane >> 2, tg = lane & 3;          // mma frag indexing

    float acc[MI][4][4];
#pragma unroll
    for (int a = 0; a < MI; a++)
#pragma unroll
        for (int b = 0; b < 4; b++)
#pragma unroll
            for (int c = 0; c < 4; c++) acc[a][b][c] = 0.f;

    float4 aldg[2], wldg[2];

    auto ldg_tile = [&](const float* __restrict__ A, const float* __restrict__ W,
                        int K, int kc) {
#pragma unroll
        for (int rep = 0; rep < 2; rep++) {
            int i = tid + rep * 256;   // 512 float4 = 128 rows x 4 segs
            int row = i >> 2, ks = i & 3;
            int m = m0 + row;
            float4 v = make_float4(0.f, 0.f, 0.f, 0.f);
            if (m < M) v = *reinterpret_cast<const float4*>(A + (size_t)m * K + kc + ks * 4);
            aldg[rep] = v;
        }
#pragma unroll
        for (int rep = 0; rep < WF4; rep++) {
            int i = tid + rep * 256;   // BK * TN/4 float4
            int kr = i / (TN / 4), ns = i % (TN / 4);
            wldg[rep] = *reinterpret_cast<const float4*>(W + (size_t)(kc + kr) * TN + ns * 4);
        }
    };
    auto sts_tile = [&](int buf) {
#pragma unroll
        for (int rep = 0; rep < 2; rep++) {
            int i = tid + rep * 256;
            int row = i >> 2, ks = i & 3;
            __nv_bfloat16 hi[4], lo[4];
            split4(aldg[rep], hi, lo);
            *reinterpret_cast<uint2*>(&As[buf][0][row][ks * 4]) = *reinterpret_cast<uint2*>(hi);
            *reinterpret_cast<uint2*>(&As[buf][1][row][ks * 4]) = *reinterpret_cast<uint2*>(lo);
        }
#pragma unroll
        for (int rep = 0; rep < WF4; rep++) {
            int i = tid + rep * 256;
            int kr = i / (TN / 4), ns = i % (TN / 4);
            __nv_bfloat16 hi[4], lo[4];
            split4(wldg[rep], hi, lo);
            *reinterpret_cast<uint2*>(&Ws[buf][0][kr][ns * 4]) = *reinterpret_cast<uint2*>(hi);
            *reinterpret_cast<uint2*>(&Ws[buf][1][kr][ns * 4]) = *reinterpret_cast<uint2*>(lo);
        }
    };
    auto compute = [&](int buf) {
        uint32_t afr[MI][2][4];
#pragma unroll
        for (int mi = 0; mi < MI; mi++)
#pragma unroll
            for (int pl = 0; pl < 2; pl++)
                ldsm_x4(afr[mi][pl],
                        smem_u32(&As[buf][pl][mw + mi * 16 + lrow][lhalf * 8]));
        uint32_t bfr[2][2][4];
#pragma unroll
        for (int ng = 0; ng < 2; ng++)
#pragma unroll
            for (int pl = 0; pl < 2; pl++)
                ldsm_x4_t(bfr[ng][pl],
                          smem_u32(&Ws[buf][pl][lrow][nw + ng * 16 + lhalf * 8]));
#pragma unroll
        for (int mi = 0; mi < MI; mi++)
#pragma unroll
            for (int ni = 0; ni < 4; ni++) {
                const uint32_t* bh = &bfr[ni >> 1][0][(ni & 1) * 2];
                const uint32_t* bl = &bfr[ni >> 1][1][(ni & 1) * 2];
                mma16816(acc[mi][ni], afr[mi][0], bh);
                mma16816(acc[mi][ni], afr[mi][0], bl);
                mma16816(acc[mi][ni], afr[mi][1], bh);
            }
    };
    auto run_piece = [&](const float* __restrict__ A, const float* __restrict__ W, int K) {
        const int nk = K / BK;
        ldg_tile(A, W, K, 0);
        sts_tile(0);
        __syncthreads();
        for (int t = 0; t < nk; t++) {
            if (t + 1 < nk) ldg_tile(A, W, K, (t + 1) * BK);
            compute(t & 1);
            if (t + 1 < nk) sts_tile((t + 1) & 1);
            __syncthreads();
        }
    };

    run_piece(A1, W1, K1);
    if (K2 > 0) run_piece(A2, W2, K2);

    // epilogue: per tile, thread holds (row g, cols 2tg/2tg+1) and (row g+8, ...)
#pragma unroll
    for (int ni = 0; ni < 4; ni++) {
        int col = nw + ni * 8 + tg * 2;
        float2 bv = make_float2(0.f, 0.f);
        if (bias) bv = *reinterpret_cast<const float2*>(bias + col);
#pragma unroll
        for (int mi = 0; mi < MI; mi++) {
#pragma unroll
            for (int half = 0; half < 2; half++) {
                int row = m0 + mw + mi * 16 + g + half * 8;
                if (row >= M) continue;
                float x0 = acc[mi][ni][half * 2 + 0] + bv.x;
                float x1 = acc[mi][ni][half * 2 + 1] + bv.y;
                if (HASADD) {
                    float2 ad = *reinterpret_cast<const float2*>(addend + (size_t)row * TN + col);
                    x0 += ad.x; x1 += ad.y;
                }
                if (RELU) { x0 = fmaxf(x0, 0.f); x1 = fmaxf(x1, 0.f); }
                float2 o = make_float2(x0, x1);
                *reinterpret_cast<float2*>(C + (size_t)row * TN + col) = o;
            }
        }
    }
}

// ---------------- launch ----------------
extern "C" void kernel_launch(void* const* d_in, const int* in_sizes, int n_in,
                              void* d_out, int out_size) {
    const float* x_txn   = (const float*)d_in[0];
    const float* x_cli   = (const float*)d_in[1];
    const int*   ct_src  = (const int*)d_in[2];
    const int*   ct_dst  = (const int*)d_in[3];
    const int*   tc_src  = (const int*)d_in[4];
    const int*   tc_dst  = (const int*)d_in[5];
    const float* W1_ct_l = (const float*)d_in[6];
    const float* b1_ct   = (const float*)d_in[7];
    const float* W1_ct_r = (const float*)d_in[8];
    const float* W1_tc_l = (const float*)d_in[9];
    const float* b1_tc   = (const float*)d_in[10];
    const float* W1_tc_r = (const float*)d_in[11];
    const float* W2_ct_l = (const float*)d_in[12];
    const float* b2_ct   = (const float*)d_in[13];
    const float* W2_ct_r = (const float*)d_in[14];
    const float* W2_tc_l = (const float*)d_in[15];
    const float* b2_tc   = (const float*)d_in[16];
    const float* W2_tc_r = (const float*)d_in[17];
    const float* Wd1     = (const float*)d_in[18];
    const float* bd1     = (const float*)d_in[19];
    const float* Wd2     = (const float*)d_in[20];
    const float* bd2     = (const float*)d_in[21];

    float* out = (float*)d_out;
    float* recon = out;
    float* z_txn = out + (size_t)N_TXN * 64;
    float* z_cli = z_txn + (size_t)N_TXN * 128;

    void* p = nullptr;
    cudaGetSymbolAddress(&p, g_iscratch);
    int* I = (int*)p;
    cudaGetSymbolAddress(&p, g_fscratch);
    float* F = (float*)p;

    int* cnt_all  = I + I_CNT_TXN;
    int* cnt_txn  = I + I_CNT_TXN;
    int* cnt_cli  = I + I_CNT_CLI;
    int* off_all  = I + I_OFF_TXN;
    int* off_txn  = I + I_OFF_TXN;
    int* off_cli  = I + I_OFF_CLI;
    int* src_base = I + I_SRC_CT;
    int* rank_ct  = I + I_RANK_CT;
    int* rank_tc  = I + I_RANK_TC;
    int* partials = I + I_PART;

    float* mean1_txn = F + F_MEAN1_TXN;
    float* mean1_cli = F + F_MEAN1_CLI;
    float* h_txn     = F + F_H_TXN;
    float* h_cli     = F + F_H_CLI;
    float* pre       = F + F_PRE;
    float* mean2_txn = F + F_MEAN2_TXN;
    float* mean2_cli = F + F_MEAN2_CLI;
    float* dec       = F + F_DEC;

    const int TB = 256;
    const int eblocks = (N_E + TB - 1) / TB;

    zero_cnt_kernel<<<(N_TOT + TB - 1) / TB, TB>>>(cnt_all);
    count_kernel<<<eblocks, TB>>>(ct_dst, tc_dst, cnt_txn, cnt_cli, rank_ct, rank_tc);
    scanA_kernel<<<SCAN_BLOCKS, 256>>>(cnt_all, off_all, partials);
    scanC_kernel<<<SCAN_BLOCKS, 256>>>(partials, off_all);
    fill_kernel<<<eblocks, TB>>>(ct_src, ct_dst, tc_src, tc_dst,
                                 rank_ct, rank_tc, off_txn, off_cli, src_base);

    mean_gather_kernel<32><<<(N_TXN * 32 + TB - 1) / TB, TB>>>(
        x_cli, src_base, off_txn, cnt_txn, mean1_txn, N_TXN);
    mean_gather_kernel<64><<<(N_CLI * 32 + TB - 1) / TB, TB>>>(
        x_txn, src_base, off_cli, cnt_cli, mean1_cli, N_CLI);

    gemm_kernel<32, 64, 128, true, false><<<(N_TXN + 127) / 128, 256>>>(
        mean1_txn, W1_ct_l, x_txn, W1_ct_r, b1_ct, nullptr, h_txn, N_TXN);
    gemm_kernel<64, 32, 128, true, false><<<(N_CLI + 127) / 128, 256>>>(
        mean1_cli, W1_tc_l, x_cli, W1_tc_r, b1_tc, nullptr, h_cli, N_CLI);

    gemm_kernel<128, 0, 128, false, false><<<(N_CLI + 127) / 128, 256>>>(
        h_cli, W2_ct_l, nullptr, nullptr, nullptr, nullptr, pre, N_CLI);
    mean_gather_kernel<128><<<(N_TXN * 32 + TB - 1) / TB, TB>>>(
        pre, src_base, off_txn, cnt_txn, mean2_txn, N_TXN);
    mean_gather_kernel<128><<<(N_CLI * 32 + TB - 1) / TB, TB>>>(
        h_txn, src_base, off_cli, cnt_cli, mean2_cli, N_CLI);

    gemm_kernel<128, 0, 128, false, true><<<(N_TXN + 127) / 128, 256>>>(
        h_txn, W2_ct_r, nullptr, nullptr, b2_ct, mean2_txn, z_txn, N_TXN);
    gemm_kernel<128, 128, 128, false, false><<<(N_CLI + 127) / 128, 256>>>(
        mean2_cli, W2_tc_l, h_cli, W2_tc_r, b2_tc, nullptr, z_cli, N_CLI);

    gemm_kernel<128, 0, 64, true, false><<<(N_TXN + 127) / 128, 256>>>(
        z_txn, Wd1, nullptr, nullptr, bd1, nullptr, dec, N_TXN);
    gemm_kernel<64, 0, 64, false, false><<<(N_TXN + 127) / 128, 256>>>(
        dec, Wd2, nullptr, nullptr, bd2, nullptr, recon, N_TXN);
}